// round 3
// baseline (speedup 1.0000x reference)
#include <cuda_runtime.h>
#include <math.h>

// Problem constants
#define BB 2
#define LL 2048
#define DM 768
#define DS 32
#define DC 7
#define DI 1536
#define BL (BB*LL)          // 4096
#define XPW (2*DS + DI)     // 1600
#define XZW (2*DI)          // 3072

// ---------------- scratch (static device globals; no allocation) ----------------
__device__ float g_xn  [BL * DM];      // layernorm output
__device__ float g_xz  [BL * XZW];     // xn @ Win^T  (xc_pre | z)
__device__ float g_xcv [BL * DI];      // conv + silu output
__device__ float g_xp  [BL * XPW];     // xcv @ Wx^T  (B | C | delta_raw)
__device__ float g_dl  [BL * DI];      // softplus(delta_raw)
__device__ float g_w   [BL * DI];      // delta * xc
__device__ float g_gate[BL * DI];      // silu(z)
__device__ float g_b2  [BL * DI];      // xc * D * silu(z)
__device__ float g_y   [BL * DI];      // scan output (gated)

// ---------------- LayerNorm ----------------
__global__ __launch_bounds__(256) void ln_kernel(
    const float* __restrict__ x, const float* __restrict__ g,
    const float* __restrict__ b)
{
    int row = blockIdx.x;
    const float* xr = x + (size_t)row * DM;
    float s = 0.f, s2 = 0.f;
    for (int i = threadIdx.x; i < DM; i += 256) {
        float v = xr[i];
        s += v; s2 += v * v;
    }
    #pragma unroll
    for (int o = 16; o; o >>= 1) {
        s  += __shfl_xor_sync(0xffffffffu, s,  o);
        s2 += __shfl_xor_sync(0xffffffffu, s2, o);
    }
    __shared__ float red[16];
    __shared__ float mu_s, rs_s;
    int wid = threadIdx.x >> 5, lane = threadIdx.x & 31;
    if (lane == 0) { red[wid] = s; red[8 + wid] = s2; }
    __syncthreads();
    if (threadIdx.x == 0) {
        float S = 0.f, S2 = 0.f;
        #pragma unroll
        for (int i = 0; i < 8; i++) { S += red[i]; S2 += red[8 + i]; }
        float mu = S / (float)DM;
        float var = S2 / (float)DM - mu * mu;
        mu_s = mu;
        rs_s = rsqrtf(var + 1e-5f);
    }
    __syncthreads();
    float mu = mu_s, rs = rs_s;
    float* orow = g_xn + (size_t)row * DM;
    for (int i = threadIdx.x; i < DM; i += 256)
        orow[i] = (xr[i] - mu) * rs * g[i] + b[i];
}

// ---------------- SGEMM: C[m,n] = sum_k A[m,k]*W[n,k] (+Cadd) ----------------
// A: MxK row-major, W: NxK row-major. BM=BN=128, BK=16, 256 thr, 8x8/thread.
__global__ __launch_bounds__(256) void sgemm_nt(
    const float* __restrict__ A, const float* __restrict__ W,
    const float* __restrict__ Cadd, float* __restrict__ C,
    int M, int N, int K)
{
    __shared__ float As[16][128];
    __shared__ float Bs[16][128];
    const int tid  = threadIdx.x;
    const int row0 = blockIdx.y * 128;
    const int col0 = blockIdx.x * 128;
    const int ldRow = tid >> 1;
    const int ldK   = (tid & 1) * 8;
    const int tx = tid & 15;
    const int ty = tid >> 4;

    const float* pA = A + (size_t)(row0 + ldRow) * K + ldK;
    const bool wvalid = (col0 + ldRow) < N;
    int wrow = wvalid ? (col0 + ldRow) : (N - 1);
    const float* pW = W + (size_t)wrow * K + ldK;

    float acc[8][8];
    #pragma unroll
    for (int i = 0; i < 8; i++)
        #pragma unroll
        for (int j = 0; j < 8; j++) acc[i][j] = 0.f;

    float4 ra0, ra1, rb0, rb1;
    ra0 = *(const float4*)(pA);
    ra1 = *(const float4*)(pA + 4);
    if (wvalid) { rb0 = *(const float4*)(pW); rb1 = *(const float4*)(pW + 4); }
    else        { rb0 = make_float4(0,0,0,0); rb1 = rb0; }

    const int ntiles = K >> 4;
    for (int kt = 0; kt < ntiles; ++kt) {
        As[ldK+0][ldRow] = ra0.x; As[ldK+1][ldRow] = ra0.y;
        As[ldK+2][ldRow] = ra0.z; As[ldK+3][ldRow] = ra0.w;
        As[ldK+4][ldRow] = ra1.x; As[ldK+5][ldRow] = ra1.y;
        As[ldK+6][ldRow] = ra1.z; As[ldK+7][ldRow] = ra1.w;
        Bs[ldK+0][ldRow] = rb0.x; Bs[ldK+1][ldRow] = rb0.y;
        Bs[ldK+2][ldRow] = rb0.z; Bs[ldK+3][ldRow] = rb0.w;
        Bs[ldK+4][ldRow] = rb1.x; Bs[ldK+5][ldRow] = rb1.y;
        Bs[ldK+6][ldRow] = rb1.z; Bs[ldK+7][ldRow] = rb1.w;
        __syncthreads();

        if (kt + 1 < ntiles) {
            pA += 16; pW += 16;
            ra0 = *(const float4*)(pA);
            ra1 = *(const float4*)(pA + 4);
            if (wvalid) { rb0 = *(const float4*)(pW); rb1 = *(const float4*)(pW + 4); }
            else        { rb0 = make_float4(0,0,0,0); rb1 = rb0; }
        }

        #pragma unroll
        for (int kk = 0; kk < 16; ++kk) {
            float4 a0 = *(const float4*)&As[kk][ty * 8];
            float4 a1 = *(const float4*)&As[kk][ty * 8 + 4];
            float4 b0 = *(const float4*)&Bs[kk][tx * 8];
            float4 b1 = *(const float4*)&Bs[kk][tx * 8 + 4];
            float av[8] = {a0.x,a0.y,a0.z,a0.w,a1.x,a1.y,a1.z,a1.w};
            float bv[8] = {b0.x,b0.y,b0.z,b0.w,b1.x,b1.y,b1.z,b1.w};
            #pragma unroll
            for (int i = 0; i < 8; i++)
                #pragma unroll
                for (int j = 0; j < 8; j++)
                    acc[i][j] = fmaf(av[i], bv[j], acc[i][j]);
        }
        __syncthreads();
    }

    #pragma unroll
    for (int i = 0; i < 8; i++) {
        int gm = row0 + ty * 8 + i;
        float* crow = C + (size_t)gm * N + col0 + tx * 8;
        const float* arow = Cadd ? (Cadd + (size_t)gm * N + col0 + tx * 8) : nullptr;
        #pragma unroll
        for (int j = 0; j < 8; j++) {
            int gn = col0 + tx * 8 + j;
            if (gn < N) {
                float v = acc[i][j];
                if (arow) v += arow[j];
                crow[j] = v;
            }
        }
    }
}

// ---------------- depthwise causal conv (DC=7) + SiLU ----------------
__global__ __launch_bounds__(256) void conv_silu_kernel(
    const float* __restrict__ cw, const float* __restrict__ cb)
{
    int idx = blockIdx.x * 256 + threadIdx.x;   // over BL*DI (grid exact)
    int d   = idx % DI;
    int row = idx / DI;           // b*L + t
    int t   = row & (LL - 1);
    float s = cb[d];
    #pragma unroll
    for (int k = 0; k < DC; k++) {
        int tt = t - (DC - 1) + k;
        if (tt >= 0)
            s = fmaf(g_xz[(size_t)(row - (DC - 1) + k) * XZW + d], cw[d * DC + k], s);
    }
    g_xcv[idx] = s / (1.f + expf(-s));
}

// ---------------- precompute: softplus(delta), delta*xc, silu(z), xc*D*silu(z) ----------------
__global__ __launch_bounds__(256) void pre_kernel(const float* __restrict__ Dv)
{
    int idx = blockIdx.x * 256 + threadIdx.x;   // over BL*DI (grid exact)
    int d   = idx % DI;
    int row = idx / DI;
    float xv = g_xp[(size_t)row * XPW + 2 * DS + d];
    float delta = fmaxf(xv, 0.f) + log1pf(expf(-fabsf(xv)));
    float xc = g_xcv[idx];
    float z  = g_xz[(size_t)row * XZW + DI + d];
    float gt = z / (1.f + expf(-z));
    g_dl[idx]   = delta;
    g_w[idx]    = delta * xc;
    g_gate[idx] = gt;
    g_b2[idx]   = xc * Dv[d] * gt;
}

// ---------------- selective scan: 1 warp per (b,d), lane = state n ----------------
__global__ __launch_bounds__(128) void scan_kernel(const float* __restrict__ A_log)
{
    int wid  = blockIdx.x * 4 + (threadIdx.x >> 5);   // 0..BB*DI-1 (grid exact)
    int lane = threadIdx.x & 31;
    int b = wid / DI;
    int d = wid - b * DI;

    // A_n premultiplied by log2(e) so dA = exp2(delta * An2)
    float An2 = -expf(A_log[d * DS + lane]) * 1.4426950408889634f;

    const float* pB  = g_xp + (size_t)b * LL * XPW + lane;
    const float* pC  = pB + DS;
    size_t base = (size_t)b * LL * DI + d;
    const float* pdl = g_dl   + base;
    const float* pw  = g_w    + base;
    const float* pg  = g_gate + base;
    const float* pb2 = g_b2   + base;
    float*       py  = g_y    + base;

    float h = 0.f;
    for (int t = 0; t < LL; ++t) {
        float Bn    = pB[0];
        float Cn    = pC[0];
        float delta = pdl[0];
        float wv    = pw[0];
        float dA = exp2f(delta * An2);
        h = fmaf(dA, h, wv * Bn);
        float p = h * Cn;
        p += __shfl_xor_sync(0xffffffffu, p, 16);
        p += __shfl_xor_sync(0xffffffffu, p, 8);
        p += __shfl_xor_sync(0xffffffffu, p, 4);
        p += __shfl_xor_sync(0xffffffffu, p, 2);
        p += __shfl_xor_sync(0xffffffffu, p, 1);
        if (lane == 0) py[0] = fmaf(p, pg[0], pb2[0]);
        pB += XPW; pC += XPW;
        pdl += DI; pw += DI; pg += DI; pb2 += DI; py += DI;
    }
}

// ---------------- launch ----------------
extern "C" void kernel_launch(void* const* d_in, const int* in_sizes, int n_in,
                              void* d_out, int out_size)
{
    (void)in_sizes; (void)n_in; (void)out_size;
    const float* x      = (const float*)d_in[0];
    const float* Win    = (const float*)d_in[1];
    const float* conv_w = (const float*)d_in[2];
    const float* conv_b = (const float*)d_in[3];
    const float* Wx     = (const float*)d_in[4];
    const float* A_log  = (const float*)d_in[5];
    const float* Dv     = (const float*)d_in[6];
    const float* Wout   = (const float*)d_in[7];
    const float* ln_g   = (const float*)d_in[8];
    const float* ln_b   = (const float*)d_in[9];
    float* out = (float*)d_out;

    void *p_xn, *p_xz, *p_xcv, *p_xp, *p_y;
    cudaGetSymbolAddress(&p_xn,  g_xn);
    cudaGetSymbolAddress(&p_xz,  g_xz);
    cudaGetSymbolAddress(&p_xcv, g_xcv);
    cudaGetSymbolAddress(&p_xp,  g_xp);
    cudaGetSymbolAddress(&p_y,   g_y);

    // 1. LayerNorm
    ln_kernel<<<BL, 256>>>(x, ln_g, ln_b);

    // 2. xz = xn @ Win^T   (4096 x 3072 x 768)
    sgemm_nt<<<dim3(XZW / 128, BL / 128), 256>>>(
        (const float*)p_xn, Win, nullptr, (float*)p_xz, BL, XZW, DM);

    // 3. depthwise conv + silu
    conv_silu_kernel<<<(BL * DI) / 256, 256>>>(conv_w, conv_b);

    // 4. xp = xcv @ Wx^T   (4096 x 1600 x 1536)
    sgemm_nt<<<dim3((XPW + 127) / 128, BL / 128), 256>>>(
        (const float*)p_xcv, Wx, nullptr, (float*)p_xp, BL, XPW, DI);

    // 5. precompute delta/gate terms
    pre_kernel<<<(BL * DI) / 256, 256>>>(Dv);

    // 6. selective scan (gated output in g_y)
    scan_kernel<<<(BB * DI) / 4, 128>>>(A_log);

    // 7. out = y @ Wout^T + x   (4096 x 768 x 1536)
    sgemm_nt<<<dim3(DM / 128, BL / 128), 256>>>(
        (const float*)p_y, Wout, x, out, BL, DM, DI);
}

// round 7
// speedup vs baseline: 1.4685x; 1.4685x over previous
#include <cuda_runtime.h>
#include <cuda_bf16.h>
#include <stdint.h>
#include <math.h>

// Problem constants
#define BB 2
#define LL 2048
#define DM 768
#define DS 32
#define DC 7
#define DI 1536
#define BL (BB*LL)          // 4096
#define XPW (2*DS + DI)     // 1600
#define XZW (2*DI)          // 3072

#define NPAD2 1664          // Wx rows padded to multiple of 128

// SMEM geometry for the GEMM: rows padded to 72 bf16 (144B) to kill bank conflicts
#define ROWB 144            // bytes per smem row (64 bf16 data + 8 pad)
#define PLANE (128*ROWB)    // 18432 B per plane
#define STAGE (4*PLANE)     // 73728 B (Ahi,Alo,Whi,Wlo)
#define SMEM_BYTES (2*STAGE) // 147456 double-buffered

// ---------------- scratch (static device globals; no allocation) ----------------
__device__ float g_xn  [BL * DM];      // layernorm output
__device__ float g_xz  [BL * XZW];     // xn @ Win^T  (xc_pre | z)
__device__ float g_xcv [BL * DI];      // conv + silu output
__device__ float g_xp  [BL * XPW];     // xcv @ Wx^T  (B | C | delta_raw)
__device__ float4 g_pack[BL * DI];     // (delta, delta*xc, silu(z), xc*D*silu(z))
__device__ float g_y   [BL * DI];      // scan output (gated)

// bf16 split planes (uint4 for 16B alignment)
__device__ uint4 g_ahi[BL * DI / 8];
__device__ uint4 g_alo[BL * DI / 8];
__device__ uint4 g_whi[NPAD2 * DI / 8];
__device__ uint4 g_wlo[NPAD2 * DI / 8];

// ==================== PTX helpers (non-'a' features only) ====================
__device__ __forceinline__ uint32_t smem_u32(const void* p) {
    uint32_t a;
    asm("{ .reg .u64 t; cvta.to.shared.u64 t, %1; cvt.u32.u64 %0, t; }"
        : "=r"(a) : "l"(p));
    return a;
}
#define CP_ASYNC16(s, g) \
    asm volatile("cp.async.cg.shared.global [%0], [%1], 16;" :: "r"(s), "l"(g) : "memory")
#define CP_COMMIT() asm volatile("cp.async.commit_group;" ::: "memory")
#define CP_WAIT0()  asm volatile("cp.async.wait_group 0;" ::: "memory")

#define MMA_BF16(acc, aa, bb) \
    asm volatile("mma.sync.aligned.m16n8k16.row.col.f32.bf16.bf16.f32 " \
        "{%0,%1,%2,%3}, {%4,%5,%6,%7}, {%8,%9}, {%0,%1,%2,%3};" \
        : "+f"((acc)[0]), "+f"((acc)[1]), "+f"((acc)[2]), "+f"((acc)[3]) \
        : "r"((aa)[0]), "r"((aa)[1]), "r"((aa)[2]), "r"((aa)[3]), \
          "r"((bb)[0]), "r"((bb)[1]))

// ==================== HMMA split-bf16 GEMM ====================
// C[m,n] = sum_k A[m,k]*W[n,k] (+Cadd). 128x128 CTA tile, 256 thr (8 warps 4Mx2N).
// K-chunk 64, cp.async double-buffered SMEM, padded rows for conflict-free LDS.
template<int K, int NVALID>
__global__ void __launch_bounds__(256, 1) tc_gemm(
    const __nv_bfloat16* __restrict__ Ahi, const __nv_bfloat16* __restrict__ Alo,
    const __nv_bfloat16* __restrict__ Whi, const __nv_bfloat16* __restrict__ Wlo,
    const float* __restrict__ Cadd, float* __restrict__ Cout)
{
    extern __shared__ char smem[];
    const int tid  = threadIdx.x;
    const int wid  = tid >> 5, lane = tid & 31;
    const int wm   = wid & 3;          // 0..3 -> 32-row slice
    const int wn   = wid >> 2;         // 0..1 -> 64-col slice
    const int tg   = lane & 3;         // thread-in-group
    const int gid  = lane >> 2;        // group id (8 groups)
    const int row0 = blockIdx.y * 128, col0 = blockIdx.x * 128;
    const uint32_t sbase = smem_u32(smem);

    // copy assignment: each thread owns (row = tid>>1, half = tid&1) -> 32 bf16 / plane
    const int crow = tid >> 1;
    const int ch   = (tid & 1) * 32;        // bf16 offset within 64
    const uint32_t soff = (uint32_t)crow * ROWB + ch * 2;   // byte offset in plane

    const __nv_bfloat16* gA  = Ahi + (size_t)(row0 + crow) * K + ch;
    const __nv_bfloat16* gAl = Alo + (size_t)(row0 + crow) * K + ch;
    const __nv_bfloat16* gW  = Whi + (size_t)(col0 + crow) * K + ch;
    const __nv_bfloat16* gWl = Wlo + (size_t)(col0 + crow) * K + ch;

    float acc[2][8][4];
    #pragma unroll
    for (int a = 0; a < 2; a++)
        #pragma unroll
        for (int b = 0; b < 8; b++)
            #pragma unroll
            for (int c = 0; c < 4; c++) acc[a][b][c] = 0.f;

    constexpr int NC = K / 64;

    // prologue: stage 0
    {
        uint32_t sb = sbase;
        #pragma unroll
        for (int i = 0; i < 4; i++) {
            CP_ASYNC16(sb + 0*PLANE + soff + i*16, gA  + i*8);
            CP_ASYNC16(sb + 1*PLANE + soff + i*16, gAl + i*8);
            CP_ASYNC16(sb + 2*PLANE + soff + i*16, gW  + i*8);
            CP_ASYNC16(sb + 3*PLANE + soff + i*16, gWl + i*8);
        }
        CP_COMMIT();
    }
    CP_WAIT0();
    __syncthreads();

    #pragma unroll 1
    for (int c = 0; c < NC; ++c) {
        // issue next chunk copy into other stage
        if (c + 1 < NC) {
            uint32_t sb = sbase + (uint32_t)((c + 1) & 1) * STAGE;
            int ko = (c + 1) * 64;
            #pragma unroll
            for (int i = 0; i < 4; i++) {
                CP_ASYNC16(sb + 0*PLANE + soff + i*16, gA  + ko + i*8);
                CP_ASYNC16(sb + 1*PLANE + soff + i*16, gAl + ko + i*8);
                CP_ASYNC16(sb + 2*PLANE + soff + i*16, gW  + ko + i*8);
                CP_ASYNC16(sb + 3*PLANE + soff + i*16, gWl + ko + i*8);
            }
            CP_COMMIT();
        }

        // compute current stage
        const char* st = smem + (size_t)(c & 1) * STAGE;
        const char* sAh = st;
        const char* sAl = st + PLANE;
        const char* sWh = st + 2*PLANE;
        const char* sWl = st + 3*PLANE;

        #pragma unroll
        for (int ks = 0; ks < 4; ks++) {
            const int k0 = ks * 16;
            uint32_t ah[2][4], al[2][4];
            #pragma unroll
            for (int mt = 0; mt < 2; mt++) {
                int ar = wm * 32 + mt * 16 + gid;
                const char* pa = sAh + ar * ROWB + (k0 + tg * 2) * 2;
                const char* pl = sAl + ar * ROWB + (k0 + tg * 2) * 2;
                ah[mt][0] = *(const uint32_t*)(pa);
                ah[mt][1] = *(const uint32_t*)(pa + 8 * ROWB);
                ah[mt][2] = *(const uint32_t*)(pa + 16);
                ah[mt][3] = *(const uint32_t*)(pa + 8 * ROWB + 16);
                al[mt][0] = *(const uint32_t*)(pl);
                al[mt][1] = *(const uint32_t*)(pl + 8 * ROWB);
                al[mt][2] = *(const uint32_t*)(pl + 16);
                al[mt][3] = *(const uint32_t*)(pl + 8 * ROWB + 16);
            }
            #pragma unroll
            for (int nt = 0; nt < 8; nt++) {
                int nr = wn * 64 + nt * 8 + gid;
                const char* pb = sWh + nr * ROWB + (k0 + tg * 2) * 2;
                const char* pc = sWl + nr * ROWB + (k0 + tg * 2) * 2;
                uint32_t bh[2], blo[2];
                bh[0]  = *(const uint32_t*)(pb);
                bh[1]  = *(const uint32_t*)(pb + 16);
                blo[0] = *(const uint32_t*)(pc);
                blo[1] = *(const uint32_t*)(pc + 16);
                #pragma unroll
                for (int mt = 0; mt < 2; mt++) {
                    MMA_BF16(acc[mt][nt], ah[mt], bh);
                    MMA_BF16(acc[mt][nt], ah[mt], blo);
                    MMA_BF16(acc[mt][nt], al[mt], bh);
                }
            }
        }
        CP_WAIT0();
        __syncthreads();
    }

    // Epilogue: direct float2 stores (col pairs are 8B-aligned since NVALID even)
    #pragma unroll
    for (int mt = 0; mt < 2; mt++) {
        #pragma unroll
        for (int nt = 0; nt < 8; nt++) {
            int row = row0 + wm * 32 + mt * 16 + gid;
            int col = col0 + wn * 64 + nt * 8 + tg * 2;
            if (col < NVALID) {
                size_t o0 = (size_t)row * NVALID + col;
                size_t o1 = (size_t)(row + 8) * NVALID + col;
                float2 v0 = make_float2(acc[mt][nt][0], acc[mt][nt][1]);
                float2 v1 = make_float2(acc[mt][nt][2], acc[mt][nt][3]);
                if (Cadd) {
                    float2 c0 = *(const float2*)(Cadd + o0);
                    float2 c1 = *(const float2*)(Cadd + o1);
                    v0.x += c0.x; v0.y += c0.y;
                    v1.x += c1.x; v1.y += c1.y;
                }
                *(float2*)(Cout + o0) = v0;
                *(float2*)(Cout + o1) = v1;
            }
        }
    }
}

// ==================== fp32 -> bf16 hi/lo split ====================
__device__ __forceinline__ uint32_t pk2(__nv_bfloat16 a, __nv_bfloat16 b) {
    unsigned short ua = *(unsigned short*)&a, ub = *(unsigned short*)&b;
    return (uint32_t)ua | ((uint32_t)ub << 16);
}
__global__ __launch_bounds__(256) void cvt_split(
    const float4* __restrict__ src, uint2* __restrict__ hi, uint2* __restrict__ lo,
    int n4, int nvalid4)
{
    int i = blockIdx.x * 256 + threadIdx.x;
    if (i >= n4) return;
    float4 v = (i < nvalid4) ? src[i] : make_float4(0.f, 0.f, 0.f, 0.f);
    __nv_bfloat16 h0 = __float2bfloat16(v.x), h1 = __float2bfloat16(v.y);
    __nv_bfloat16 h2 = __float2bfloat16(v.z), h3 = __float2bfloat16(v.w);
    __nv_bfloat16 l0 = __float2bfloat16(v.x - __bfloat162float(h0));
    __nv_bfloat16 l1 = __float2bfloat16(v.y - __bfloat162float(h1));
    __nv_bfloat16 l2 = __float2bfloat16(v.z - __bfloat162float(h2));
    __nv_bfloat16 l3 = __float2bfloat16(v.w - __bfloat162float(h3));
    uint2 H, L;
    H.x = pk2(h0, h1); H.y = pk2(h2, h3);
    L.x = pk2(l0, l1); L.y = pk2(l2, l3);
    hi[i] = H; lo[i] = L;
}

// ---------------- LayerNorm ----------------
__global__ __launch_bounds__(256) void ln_kernel(
    const float* __restrict__ x, const float* __restrict__ g,
    const float* __restrict__ b)
{
    int row = blockIdx.x;
    const float* xr = x + (size_t)row * DM;
    float s = 0.f, s2 = 0.f;
    for (int i = threadIdx.x; i < DM; i += 256) {
        float v = xr[i];
        s += v; s2 += v * v;
    }
    #pragma unroll
    for (int o = 16; o; o >>= 1) {
        s  += __shfl_xor_sync(0xffffffffu, s,  o);
        s2 += __shfl_xor_sync(0xffffffffu, s2, o);
    }
    __shared__ float red[16];
    __shared__ float mu_s, rs_s;
    int wid = threadIdx.x >> 5, lane = threadIdx.x & 31;
    if (lane == 0) { red[wid] = s; red[8 + wid] = s2; }
    __syncthreads();
    if (threadIdx.x == 0) {
        float S = 0.f, S2 = 0.f;
        #pragma unroll
        for (int i = 0; i < 8; i++) { S += red[i]; S2 += red[8 + i]; }
        float mu = S / (float)DM;
        float var = S2 / (float)DM - mu * mu;
        mu_s = mu;
        rs_s = rsqrtf(var + 1e-5f);
    }
    __syncthreads();
    float mu = mu_s, rs = rs_s;
    float* orow = g_xn + (size_t)row * DM;
    for (int i = threadIdx.x; i < DM; i += 256)
        orow[i] = (xr[i] - mu) * rs * g[i] + b[i];
}

// ---------------- depthwise causal conv (DC=7) + SiLU ----------------
__global__ __launch_bounds__(256) void conv_silu_kernel(
    const float* __restrict__ cw, const float* __restrict__ cb)
{
    int idx = blockIdx.x * 256 + threadIdx.x;
    int d   = idx % DI;
    int row = idx / DI;
    int t   = row & (LL - 1);
    float s = cb[d];
    #pragma unroll
    for (int k = 0; k < DC; k++) {
        int tt = t - (DC - 1) + k;
        if (tt >= 0)
            s = fmaf(g_xz[(size_t)(row - (DC - 1) + k) * XZW + d], cw[d * DC + k], s);
    }
    g_xcv[idx] = s / (1.f + __expf(-s));
}

// ---------------- precompute packed scan inputs ----------------
__global__ __launch_bounds__(256) void pre_kernel(const float* __restrict__ Dv)
{
    int idx = blockIdx.x * 256 + threadIdx.x;
    int d   = idx % DI;
    int row = idx / DI;
    float xv = g_xp[(size_t)row * XPW + 2 * DS + d];
    float delta = (xv > 15.f) ? xv : __logf(1.f + __expf(xv));
    float xc = g_xcv[idx];
    float z  = g_xz[(size_t)row * XZW + DI + d];
    float gt = z / (1.f + __expf(-z));
    g_pack[idx] = make_float4(delta, delta * xc, gt, xc * Dv[d] * gt);
}

// ---------------- selective scan: 1 warp per (b,d), lane = state n ----------------
__global__ __launch_bounds__(128) void scan_kernel(const float* __restrict__ A_log)
{
    int wid  = blockIdx.x * 4 + (threadIdx.x >> 5);
    int lane = threadIdx.x & 31;
    int b = wid / DI;
    int d = wid - b * DI;

    float An2 = -__expf(A_log[d * DS + lane]) * 1.4426950408889634f;

    const float*  pB = g_xp   + (size_t)b * LL * XPW + lane;
    const float4* pk = g_pack + (size_t)b * LL * DI + d;
    float*        py = g_y    + (size_t)b * LL * DI + d;

    float h = 0.f;
    #pragma unroll 4
    for (int t = 0; t < LL; ++t) {
        float Bn = pB[0];
        float Cn = pB[DS];
        float4 P = *pk;
        float dA = exp2f(P.x * An2);
        h = fmaf(dA, h, P.y * Bn);
        float p = h * Cn;
        p += __shfl_xor_sync(0xffffffffu, p, 16);
        p += __shfl_xor_sync(0xffffffffu, p, 8);
        p += __shfl_xor_sync(0xffffffffu, p, 4);
        p += __shfl_xor_sync(0xffffffffu, p, 2);
        p += __shfl_xor_sync(0xffffffffu, p, 1);
        if (lane == 0) *py = fmaf(p, P.z, P.w);
        pB += XPW; pk += DI; py += DI;
    }
}

// ---------------- launch ----------------
extern "C" void kernel_launch(void* const* d_in, const int* in_sizes, int n_in,
                              void* d_out, int out_size)
{
    (void)in_sizes; (void)n_in; (void)out_size;
    const float* x      = (const float*)d_in[0];
    const float* Win    = (const float*)d_in[1];
    const float* conv_w = (const float*)d_in[2];
    const float* conv_b = (const float*)d_in[3];
    const float* Wx     = (const float*)d_in[4];
    const float* A_log  = (const float*)d_in[5];
    const float* Dv     = (const float*)d_in[6];
    const float* Wout   = (const float*)d_in[7];
    const float* ln_g   = (const float*)d_in[8];
    const float* ln_b   = (const float*)d_in[9];
    float* out = (float*)d_out;

    void *p_xn, *p_xz, *p_xcv, *p_xp, *p_y, *p_ahi, *p_alo, *p_whi, *p_wlo;
    cudaGetSymbolAddress(&p_xn,  g_xn);
    cudaGetSymbolAddress(&p_xz,  g_xz);
    cudaGetSymbolAddress(&p_xcv, g_xcv);
    cudaGetSymbolAddress(&p_xp,  g_xp);
    cudaGetSymbolAddress(&p_y,   g_y);
    cudaGetSymbolAddress(&p_ahi, g_ahi);
    cudaGetSymbolAddress(&p_alo, g_alo);
    cudaGetSymbolAddress(&p_whi, g_whi);
    cudaGetSymbolAddress(&p_wlo, g_wlo);

    const __nv_bfloat16* ahi = (const __nv_bfloat16*)p_ahi;
    const __nv_bfloat16* alo = (const __nv_bfloat16*)p_alo;
    const __nv_bfloat16* whi = (const __nv_bfloat16*)p_whi;
    const __nv_bfloat16* wlo = (const __nv_bfloat16*)p_wlo;

    cudaFuncSetAttribute((const void*)tc_gemm<768, 3072>,
                         cudaFuncAttributeMaxDynamicSharedMemorySize, SMEM_BYTES);
    cudaFuncSetAttribute((const void*)tc_gemm<1536, 1600>,
                         cudaFuncAttributeMaxDynamicSharedMemorySize, SMEM_BYTES);
    cudaFuncSetAttribute((const void*)tc_gemm<1536, 768>,
                         cudaFuncAttributeMaxDynamicSharedMemorySize, SMEM_BYTES);

    // 1. LayerNorm
    ln_kernel<<<BL, 256>>>(x, ln_g, ln_b);

    // 2. split-convert xn (4096x768) and Win (3072x768)
    cvt_split<<<3072, 256>>>((const float4*)p_xn, (uint2*)p_ahi, (uint2*)p_alo,
                             786432, 786432);
    cvt_split<<<2304, 256>>>((const float4*)Win, (uint2*)p_whi, (uint2*)p_wlo,
                             589824, 589824);

    // 3. xz = xn @ Win^T   (4096 x 3072 x 768)
    tc_gemm<768, 3072><<<dim3(24, 32), 256, SMEM_BYTES>>>(
        ahi, alo, whi, wlo, nullptr, (float*)p_xz);

    // 4. depthwise conv + silu
    conv_silu_kernel<<<(BL * DI) / 256, 256>>>(conv_w, conv_b);

    // 5. split-convert xcv (4096x1536) and Wx (1600x1536 -> padded 1664)
    cvt_split<<<6144, 256>>>((const float4*)p_xcv, (uint2*)p_ahi, (uint2*)p_alo,
                             1572864, 1572864);
    cvt_split<<<2496, 256>>>((const float4*)Wx, (uint2*)p_whi, (uint2*)p_wlo,
                             638976, 614400);

    // 6. xp = xcv @ Wx^T   (4096 x 1600 x 1536)
    tc_gemm<1536, 1600><<<dim3(13, 32), 256, SMEM_BYTES>>>(
        ahi, alo, whi, wlo, nullptr, (float*)p_xp);

    // 7. precompute packed scan inputs
    pre_kernel<<<(BL * DI) / 256, 256>>>(Dv);

    // 8. selective scan
    scan_kernel<<<(BB * DI) / 4, 128>>>(A_log);

    // 9. split-convert y (4096x1536) and Wout (768x1536)
    cvt_split<<<6144, 256>>>((const float4*)p_y, (uint2*)p_ahi, (uint2*)p_alo,
                             1572864, 1572864);
    cvt_split<<<1152, 256>>>((const float4*)Wout, (uint2*)p_whi, (uint2*)p_wlo,
                             294912, 294912);

    // 10. out = y @ Wout^T + x   (4096 x 768 x 1536)
    tc_gemm<1536, 768><<<dim3(6, 32), 256, SMEM_BYTES>>>(
        ahi, alo, whi, wlo, x, out);
}

// round 8
// speedup vs baseline: 1.6027x; 1.0914x over previous
#include <cuda_runtime.h>
#include <cuda_bf16.h>
#include <stdint.h>
#include <math.h>

// Problem constants
#define BB 2
#define LL 2048
#define DM 768
#define DS 32
#define DC 7
#define DI 1536
#define BL (BB*LL)          // 4096
#define XPW (2*DS + DI)     // 1600
#define XZW (2*DI)          // 3072

#define NPAD2 1664          // Wx rows padded to multiple of 128

// SMEM geometry: K-chunk 32 bf16 = 64B data + 16B pad per row
#define ROWB 80
#define PLANE (128*ROWB)      // 10240 B
#define STAGE (4*PLANE)       // 40960 B (Ahi,Alo,Whi,Wlo)
#define SMEM_BYTES (2*STAGE)  // 81920 double-buffered -> 2 CTAs/SM

// ---------------- scratch (static device globals; no allocation) ----------------
__device__ float g_xz  [BL * XZW];     // xn @ Win^T  (xc_pre | z)
__device__ float g_xp  [BL * XPW];     // xcv @ Wx^T  (B | C | delta_raw)
__device__ float4 g_pack[BL * DI];     // (delta, delta*xc, silu(z), xc*D*silu(z))

// bf16 split planes: A-side reused for xn -> xcv -> y ; W-side for Win -> Wx -> Wout
__device__ __align__(16) __nv_bfloat16 g_ahi[BL * DI];
__device__ __align__(16) __nv_bfloat16 g_alo[BL * DI];
__device__ __align__(16) __nv_bfloat16 g_whi[NPAD2 * DI];
__device__ __align__(16) __nv_bfloat16 g_wlo[NPAD2 * DI];

// ==================== PTX helpers (non-'a' features only) ====================
__device__ __forceinline__ uint32_t smem_u32(const void* p) {
    uint32_t a;
    asm("{ .reg .u64 t; cvta.to.shared.u64 t, %1; cvt.u32.u64 %0, t; }"
        : "=r"(a) : "l"(p));
    return a;
}
#define CP_ASYNC16(s, g) \
    asm volatile("cp.async.cg.shared.global [%0], [%1], 16;" :: "r"(s), "l"(g) : "memory")
#define CP_COMMIT() asm volatile("cp.async.commit_group;" ::: "memory")
#define CP_WAITG(n) asm volatile("cp.async.wait_group %0;" :: "n"(n) : "memory")

#define LDMX4(r0, r1, r2, r3, a) \
    asm volatile("ldmatrix.sync.aligned.m8n8.x4.shared.b16 {%0,%1,%2,%3}, [%4];" \
        : "=r"(r0), "=r"(r1), "=r"(r2), "=r"(r3) : "r"(a))

#define MMA_BF16(acc, aa, b0, b1) \
    asm volatile("mma.sync.aligned.m16n8k16.row.col.f32.bf16.bf16.f32 " \
        "{%0,%1,%2,%3}, {%4,%5,%6,%7}, {%8,%9}, {%0,%1,%2,%3};" \
        : "+f"((acc)[0]), "+f"((acc)[1]), "+f"((acc)[2]), "+f"((acc)[3]) \
        : "r"((aa)[0]), "r"((aa)[1]), "r"((aa)[2]), "r"((aa)[3]), \
          "r"(b0), "r"(b1))

// ==================== HMMA split-bf16 GEMM ====================
// C[m,n] = sum_k A[m,k]*W[n,k] (+Cadd). 128x128 CTA tile, 256 thr (8 warps 4Mx2N),
// K-chunk 32, cp.async double-buffered (overlapped via wait_group 1), ldmatrix frags.
__device__ __forceinline__ void stage_copy(
    uint32_t sb, const __nv_bfloat16* gA, const __nv_bfloat16* gAl,
    const __nv_bfloat16* gW, const __nv_bfloat16* gWl, int Kst, int tid)
{
    #pragma unroll
    for (int h = 0; h < 2; h++) {
        int c = tid + h * 256;
        int row = c >> 2, part = c & 3;
        uint32_t so = (uint32_t)row * ROWB + part * 16;
        size_t go = (size_t)row * Kst + part * 8;
        CP_ASYNC16(sb + 0*PLANE + so, gA  + go);
        CP_ASYNC16(sb + 1*PLANE + so, gAl + go);
        CP_ASYNC16(sb + 2*PLANE + so, gW  + go);
        CP_ASYNC16(sb + 3*PLANE + so, gWl + go);
    }
}

template<int K, int NVALID>
__global__ void __launch_bounds__(256, 2) tc_gemm(
    const __nv_bfloat16* __restrict__ Ahi, const __nv_bfloat16* __restrict__ Alo,
    const __nv_bfloat16* __restrict__ Whi, const __nv_bfloat16* __restrict__ Wlo,
    const float* __restrict__ Cadd, float* __restrict__ Cout)
{
    extern __shared__ char smem[];
    const int tid  = threadIdx.x;
    const int wid  = tid >> 5, lane = tid & 31;
    const int wm   = wid & 3;          // 0..3 -> 32-row slice
    const int wn   = wid >> 2;         // 0..1 -> 64-col slice
    const int row0 = blockIdx.y * 128, col0 = blockIdx.x * 128;
    const uint32_t sbase = smem_u32(smem);

    const __nv_bfloat16* pA  = Ahi + (size_t)row0 * K;
    const __nv_bfloat16* pAl = Alo + (size_t)row0 * K;
    const __nv_bfloat16* pW  = Whi + (size_t)col0 * K;
    const __nv_bfloat16* pWl = Wlo + (size_t)col0 * K;

    // ldmatrix lane addressing
    const int lr  = lane & 7;
    const int mlo = (lane >> 3) & 1;   // matrix index low bit
    const int mhi = (lane >> 4) & 1;   // matrix index high bit
    uint32_t aoff[2], boff[4];
    #pragma unroll
    for (int mt = 0; mt < 2; mt++)
        aoff[mt] = (uint32_t)(wm * 32 + mt * 16 + lr + mlo * 8) * ROWB + mhi * 16;
    #pragma unroll
    for (int np = 0; np < 4; np++)
        boff[np] = (uint32_t)(wn * 64 + np * 16 + lr + mhi * 8) * ROWB + mlo * 16;

    float acc[2][8][4];
    #pragma unroll
    for (int a = 0; a < 2; a++)
        #pragma unroll
        for (int b = 0; b < 8; b++)
            #pragma unroll
            for (int c = 0; c < 4; c++) acc[a][b][c] = 0.f;

    constexpr int NC = K / 32;

    stage_copy(sbase, pA, pAl, pW, pWl, K, tid);
    CP_COMMIT();

    #pragma unroll 1
    for (int c = 0; c < NC; ++c) {
        if (c + 1 < NC) {
            int ko = (c + 1) * 32;
            stage_copy(sbase + (uint32_t)((c + 1) & 1) * STAGE,
                       pA + ko, pAl + ko, pW + ko, pWl + ko, K, tid);
            CP_COMMIT();
            CP_WAITG(1);      // wait for chunk c only; chunk c+1 stays in flight
        } else {
            CP_WAITG(0);
        }
        __syncthreads();

        const uint32_t st = sbase + (uint32_t)(c & 1) * STAGE;
        #pragma unroll
        for (int ks = 0; ks < 2; ks++) {
            const uint32_t kb = ks * 32;   // 16 bf16 = 32 bytes
            uint32_t ah[2][4], al[2][4];
            #pragma unroll
            for (int mt = 0; mt < 2; mt++) {
                LDMX4(ah[mt][0], ah[mt][1], ah[mt][2], ah[mt][3],
                      st + 0*PLANE + aoff[mt] + kb);
                LDMX4(al[mt][0], al[mt][1], al[mt][2], al[mt][3],
                      st + 1*PLANE + aoff[mt] + kb);
            }
            #pragma unroll
            for (int np = 0; np < 4; np++) {
                uint32_t bh[4], bl[4];
                LDMX4(bh[0], bh[1], bh[2], bh[3], st + 2*PLANE + boff[np] + kb);
                LDMX4(bl[0], bl[1], bl[2], bl[3], st + 3*PLANE + boff[np] + kb);
                #pragma unroll
                for (int h = 0; h < 2; h++) {
                    const int nt = np * 2 + h;
                    #pragma unroll
                    for (int mt = 0; mt < 2; mt++) {
                        MMA_BF16(acc[mt][nt], ah[mt], bh[2*h], bh[2*h+1]);
                        MMA_BF16(acc[mt][nt], ah[mt], bl[2*h], bl[2*h+1]);
                        MMA_BF16(acc[mt][nt], al[mt], bh[2*h], bh[2*h+1]);
                    }
                }
            }
        }
        __syncthreads();
    }

    // Epilogue: direct float2 stores
    const int tg = lane & 3, gid = lane >> 2;
    #pragma unroll
    for (int mt = 0; mt < 2; mt++) {
        #pragma unroll
        for (int nt = 0; nt < 8; nt++) {
            int row = row0 + wm * 32 + mt * 16 + gid;
            int col = col0 + wn * 64 + nt * 8 + tg * 2;
            if (col < NVALID) {
                size_t o0 = (size_t)row * NVALID + col;
                size_t o1 = (size_t)(row + 8) * NVALID + col;
                float2 v0 = make_float2(acc[mt][nt][0], acc[mt][nt][1]);
                float2 v1 = make_float2(acc[mt][nt][2], acc[mt][nt][3]);
                if (Cadd) {
                    float2 c0 = *(const float2*)(Cadd + o0);
                    float2 c1 = *(const float2*)(Cadd + o1);
                    v0.x += c0.x; v0.y += c0.y;
                    v1.x += c1.x; v1.y += c1.y;
                }
                *(float2*)(Cout + o0) = v0;
                *(float2*)(Cout + o1) = v1;
            }
        }
    }
}

// ==================== fp32 -> bf16 hi/lo split (weights only) ====================
__device__ __forceinline__ uint32_t pk2(__nv_bfloat16 a, __nv_bfloat16 b) {
    unsigned short ua = *(unsigned short*)&a, ub = *(unsigned short*)&b;
    return (uint32_t)ua | ((uint32_t)ub << 16);
}
__global__ __launch_bounds__(256) void cvt_split(
    const float4* __restrict__ src, uint2* __restrict__ hi, uint2* __restrict__ lo,
    int n4, int nvalid4)
{
    int i = blockIdx.x * 256 + threadIdx.x;
    if (i >= n4) return;
    float4 v = (i < nvalid4) ? src[i] : make_float4(0.f, 0.f, 0.f, 0.f);
    __nv_bfloat16 h0 = __float2bfloat16(v.x), h1 = __float2bfloat16(v.y);
    __nv_bfloat16 h2 = __float2bfloat16(v.z), h3 = __float2bfloat16(v.w);
    __nv_bfloat16 l0 = __float2bfloat16(v.x - __bfloat162float(h0));
    __nv_bfloat16 l1 = __float2bfloat16(v.y - __bfloat162float(h1));
    __nv_bfloat16 l2 = __float2bfloat16(v.z - __bfloat162float(h2));
    __nv_bfloat16 l3 = __float2bfloat16(v.w - __bfloat162float(h3));
    uint2 H, L;
    H.x = pk2(h0, h1); H.y = pk2(h2, h3);
    L.x = pk2(l0, l1); L.y = pk2(l2, l3);
    hi[i] = H; lo[i] = L;
}

// ---------------- LayerNorm -> bf16 hi/lo planes ----------------
__global__ __launch_bounds__(256) void ln_kernel(
    const float* __restrict__ x, const float* __restrict__ g,
    const float* __restrict__ b)
{
    int row = blockIdx.x;
    const float* xr = x + (size_t)row * DM;
    float s = 0.f, s2 = 0.f;
    for (int i = threadIdx.x; i < DM; i += 256) {
        float v = xr[i];
        s += v; s2 += v * v;
    }
    #pragma unroll
    for (int o = 16; o; o >>= 1) {
        s  += __shfl_xor_sync(0xffffffffu, s,  o);
        s2 += __shfl_xor_sync(0xffffffffu, s2, o);
    }
    __shared__ float red[16];
    __shared__ float mu_s, rs_s;
    int wid = threadIdx.x >> 5, lane = threadIdx.x & 31;
    if (lane == 0) { red[wid] = s; red[8 + wid] = s2; }
    __syncthreads();
    if (threadIdx.x == 0) {
        float S = 0.f, S2 = 0.f;
        #pragma unroll
        for (int i = 0; i < 8; i++) { S += red[i]; S2 += red[8 + i]; }
        float mu = S / (float)DM;
        float var = S2 / (float)DM - mu * mu;
        mu_s = mu;
        rs_s = rsqrtf(var + 1e-5f);
    }
    __syncthreads();
    float mu = mu_s, rs = rs_s;
    for (int i = threadIdx.x; i < DM; i += 256) {
        float v = (xr[i] - mu) * rs * g[i] + b[i];
        __nv_bfloat16 h = __float2bfloat16(v);
        g_ahi[(size_t)row * DM + i] = h;
        g_alo[(size_t)row * DM + i] = __float2bfloat16(v - __bfloat162float(h));
    }
}

// ---------------- depthwise causal conv (DC=7) + SiLU -> bf16 hi/lo ----------------
__global__ __launch_bounds__(256) void conv_silu_kernel(
    const float* __restrict__ cw, const float* __restrict__ cb)
{
    int idx = blockIdx.x * 256 + threadIdx.x;
    int d   = idx % DI;
    int row = idx / DI;
    int t   = row & (LL - 1);
    float s = cb[d];
    #pragma unroll
    for (int k = 0; k < DC; k++) {
        int tt = t - (DC - 1) + k;
        if (tt >= 0)
            s = fmaf(g_xz[(size_t)(row - (DC - 1) + k) * XZW + d], cw[d * DC + k], s);
    }
    float r = s / (1.f + __expf(-s));
    __nv_bfloat16 h = __float2bfloat16(r);
    g_ahi[idx] = h;
    g_alo[idx] = __float2bfloat16(r - __bfloat162float(h));
}

// ---------------- precompute packed scan inputs (xc from hi/lo planes) ----------------
__global__ __launch_bounds__(256) void pre_kernel(const float* __restrict__ Dv)
{
    int idx = blockIdx.x * 256 + threadIdx.x;
    int d   = idx % DI;
    int row = idx / DI;
    float xv = g_xp[(size_t)row * XPW + 2 * DS + d];
    float delta = (xv > 15.f) ? xv : __logf(1.f + __expf(xv));
    float xc = __bfloat162float(g_ahi[idx]) + __bfloat162float(g_alo[idx]);
    float z  = g_xz[(size_t)row * XZW + DI + d];
    float gt = z / (1.f + __expf(-z));
    g_pack[idx] = make_float4(delta, delta * xc, gt, xc * Dv[d] * gt);
}

// ---------------- selective scan: 1 warp per (b,d), lane = state n; y -> bf16 hi/lo --
__global__ __launch_bounds__(128) void scan_kernel(const float* __restrict__ A_log)
{
    int wid  = blockIdx.x * 4 + (threadIdx.x >> 5);
    int lane = threadIdx.x & 31;
    int b = wid / DI;
    int d = wid - b * DI;

    float An2 = -__expf(A_log[d * DS + lane]) * 1.4426950408889634f;

    const float*  pB = g_xp   + (size_t)b * LL * XPW + lane;
    const float4* pk = g_pack + (size_t)b * LL * DI + d;
    __nv_bfloat16* pyh = g_ahi + (size_t)b * LL * DI + d;
    __nv_bfloat16* pyl = g_alo + (size_t)b * LL * DI + d;

    float h = 0.f;
    #pragma unroll 4
    for (int t = 0; t < LL; ++t) {
        float Bn = pB[0];
        float Cn = pB[DS];
        float4 P = *pk;
        float dA = exp2f(P.x * An2);
        h = fmaf(dA, h, P.y * Bn);
        float p = h * Cn;
        p += __shfl_xor_sync(0xffffffffu, p, 16);
        p += __shfl_xor_sync(0xffffffffu, p, 8);
        p += __shfl_xor_sync(0xffffffffu, p, 4);
        p += __shfl_xor_sync(0xffffffffu, p, 2);
        p += __shfl_xor_sync(0xffffffffu, p, 1);
        if (lane == 0) {
            float yv = fmaf(p, P.z, P.w);
            __nv_bfloat16 yh = __float2bfloat16(yv);
            pyh[0] = yh;
            pyl[0] = __float2bfloat16(yv - __bfloat162float(yh));
        }
        pB += XPW; pk += DI; pyh += DI; pyl += DI;
    }
}

// ---------------- launch ----------------
extern "C" void kernel_launch(void* const* d_in, const int* in_sizes, int n_in,
                              void* d_out, int out_size)
{
    (void)in_sizes; (void)n_in; (void)out_size;
    const float* x      = (const float*)d_in[0];
    const float* Win    = (const float*)d_in[1];
    const float* conv_w = (const float*)d_in[2];
    const float* conv_b = (const float*)d_in[3];
    const float* Wx     = (const float*)d_in[4];
    const float* A_log  = (const float*)d_in[5];
    const float* Dv     = (const float*)d_in[6];
    const float* Wout   = (const float*)d_in[7];
    const float* ln_g   = (const float*)d_in[8];
    const float* ln_b   = (const float*)d_in[9];
    float* out = (float*)d_out;

    void *p_xz, *p_xp, *p_ahi, *p_alo, *p_whi, *p_wlo;
    cudaGetSymbolAddress(&p_xz,  g_xz);
    cudaGetSymbolAddress(&p_xp,  g_xp);
    cudaGetSymbolAddress(&p_ahi, g_ahi);
    cudaGetSymbolAddress(&p_alo, g_alo);
    cudaGetSymbolAddress(&p_whi, g_whi);
    cudaGetSymbolAddress(&p_wlo, g_wlo);

    const __nv_bfloat16* ahi = (const __nv_bfloat16*)p_ahi;
    const __nv_bfloat16* alo = (const __nv_bfloat16*)p_alo;
    const __nv_bfloat16* whi = (const __nv_bfloat16*)p_whi;
    const __nv_bfloat16* wlo = (const __nv_bfloat16*)p_wlo;

    cudaFuncSetAttribute((const void*)tc_gemm<768, 3072>,
                         cudaFuncAttributeMaxDynamicSharedMemorySize, SMEM_BYTES);
    cudaFuncSetAttribute((const void*)tc_gemm<1536, 1600>,
                         cudaFuncAttributeMaxDynamicSharedMemorySize, SMEM_BYTES);
    cudaFuncSetAttribute((const void*)tc_gemm<1536, 768>,
                         cudaFuncAttributeMaxDynamicSharedMemorySize, SMEM_BYTES);

    // 1. LayerNorm (writes xn hi/lo planes directly)
    ln_kernel<<<BL, 256>>>(x, ln_g, ln_b);

    // 2. split-convert Win (3072x768)
    cvt_split<<<2304, 256>>>((const float4*)Win, (uint2*)p_whi, (uint2*)p_wlo,
                             589824, 589824);

    // 3. xz = xn @ Win^T   (4096 x 3072 x 768)
    tc_gemm<768, 3072><<<dim3(24, 32), 256, SMEM_BYTES>>>(
        ahi, alo, whi, wlo, nullptr, (float*)p_xz);

    // 4. depthwise conv + silu (writes xcv hi/lo planes directly)
    conv_silu_kernel<<<(BL * DI) / 256, 256>>>(conv_w, conv_b);

    // 5. split-convert Wx (1600x1536 -> padded 1664)
    cvt_split<<<2496, 256>>>((const float4*)Wx, (uint2*)p_whi, (uint2*)p_wlo,
                             638976, 614400);

    // 6. xp = xcv @ Wx^T   (4096 x 1600 x 1536)
    tc_gemm<1536, 1600><<<dim3(13, 32), 256, SMEM_BYTES>>>(
        ahi, alo, whi, wlo, nullptr, (float*)p_xp);

    // 7. precompute packed scan inputs
    pre_kernel<<<(BL * DI) / 256, 256>>>(Dv);

    // 8. selective scan (writes y hi/lo planes directly)
    scan_kernel<<<(BB * DI) / 4, 128>>>(A_log);

    // 9. split-convert Wout (768x1536)
    cvt_split<<<1152, 256>>>((const float4*)Wout, (uint2*)p_whi, (uint2*)p_wlo,
                             294912, 294912);

    // 10. out = y @ Wout^T + x   (4096 x 768 x 1536)
    tc_gemm<1536, 768><<<dim3(6, 32), 256, SMEM_BYTES>>>(
        ahi, alo, whi, wlo, x, out);
}